// round 3
// baseline (speedup 1.0000x reference)
#include <cuda_runtime.h>
#include <cuda_fp16.h>
#include <math.h>

// Problem dims (fixed by the dataset)
#define NN 4
#define HH 512
#define WW 512
#define CC 64

#define CPB     16                 // channels per block
#define THREADS 512
#define ROWLEN  512                // scan length (W in pass1, H in pass2)
#define NCHUNK  (THREADS / CPB)    // 32
#define CLEN    (ROWLEN / NCHUNK)  // 16
#define LWARM   24                 // warm-up: err ~ 0.5^24 ~ 6e-8
#define VEC     (ROWLEN * CPB / 4) // float4s per fp32 tile = 2048
#define VECH    (ROWLEN * CPB / 8) // uint4s (8 halves) per fp16 tile = 1024
#define SMEM_BYTES (ROWLEN * CPB * 4) // 32768

// Intermediate (W-filtered) image in fp16, same NHWC index space as x.
__device__ __half g_scratch[(size_t)NN * HH * WW * CC];

// Forward+backward first-order IIR (a=b=0.5) over a ROWLEN x CPB fp32 tile
// in shared memory, in place. Chunk-parallel with clamped warm-ups that make
// the boundary chunks EXACT:
//   forward:  ws = max(w0-LWARM, 0); chunk 0 gets carry = s[0] = x[0] (exact
//             reference init c0 = x[0], so y_f[0] = x[0]).
//   backward: we = min(w1-1+LWARM, L-1); chunks reaching the end start from
//             carry = s[L-1] = y_f[L-1] = y_b[L-1] (exact reference init).
// Interior chunks decay their carry guess over >= LWARM-1 steps (<= 1.2e-7).
__device__ __forceinline__ void iir_scan_tile(float* s, int tid) {
    const int c     = tid & (CPB - 1);
    const int chunk = tid / CPB;          // 0..NCHUNK-1
    const int w0    = chunk * CLEN;
    const int w1    = w0 + CLEN;

    // ---- forward warm-up (read-only) ----
    int ws = w0 - LWARM; if (ws < 0) ws = 0;
    float carry = s[ws * CPB + c];
    for (int w = ws; w < w0; ++w)
        carry = fmaf(0.5f, carry, 0.5f * s[w * CPB + c]);
    __syncthreads();

    // ---- forward scan, in place (own chunk only) ----
    #pragma unroll
    for (int w = w0; w < w1; ++w) {
        carry = fmaf(0.5f, carry, 0.5f * s[w * CPB + c]);
        s[w * CPB + c] = carry;
    }
    __syncthreads();

    // ---- backward warm-up (read-only on finalized y_f) ----
    int we = w1 - 1 + LWARM; if (we > ROWLEN - 1) we = ROWLEN - 1;
    carry = s[we * CPB + c];
    for (int w = we - 1; w >= w1; --w)
        carry = fmaf(0.5f, carry, 0.5f * s[w * CPB + c]);
    __syncthreads();

    // ---- backward scan, in place (own chunk only) ----
    #pragma unroll
    for (int w = w1 - 1; w >= w0; --w) {
        carry = fmaf(0.5f, carry, 0.5f * s[w * CPB + c]);
        s[w * CPB + c] = carry;
    }
    __syncthreads();
}

// Pass 1: IIR along W. One block per (n*H row, channel-group of 16).
// Reads x (fp32), writes W-filtered tile to g_scratch (fp16).
__global__ void __launch_bounds__(THREADS, 4)
pass1_kernel(const float* __restrict__ x) {
    extern __shared__ float s[];
    float4* s4 = reinterpret_cast<float4*>(s);

    const int    nh   = blockIdx.x;                 // n*HH + h
    const int    cg   = blockIdx.y;                 // channel group
    const size_t base = (size_t)nh * (WW * CC) + (size_t)cg * CPB;

    #pragma unroll
    for (int i = threadIdx.x; i < VEC; i += THREADS) {
        const int w  = i >> 2;                      // 4 float4 per w
        const int c4 = i & 3;
        s4[w * 4 + c4] = *(const float4*)(x + base + (size_t)w * CC + c4 * 4);
    }
    __syncthreads();

    iir_scan_tile(s, threadIdx.x);

    // fp16 store: per w, 16 ch = 32B = 2 uint4 (8 halves each)
    #pragma unroll
    for (int i = threadIdx.x; i < VECH; i += THREADS) {
        const int w = i >> 1;
        const int q = i & 1;
        const float* sp = s + w * CPB + q * 8;
        __half2 hv[4];
        #pragma unroll
        for (int k = 0; k < 4; ++k)
            hv[k] = __floats2half2_rn(sp[2 * k], sp[2 * k + 1]);
        *(uint4*)(g_scratch + base + (size_t)w * CC + q * 8) = *(uint4*)hv;
    }
}

// Pass 2: IIR along H on the scratch (fp16 in, fp32 scan), residual mix -> out.
__global__ void __launch_bounds__(THREADS, 4)
pass2_kernel(const float* __restrict__ x,
             const float* __restrict__ alpha,
             float*       __restrict__ out) {
    extern __shared__ float s[];
    float4* s4 = reinterpret_cast<float4*>(s);
    __shared__ __align__(16) float sm[CPB];

    const int    nw   = blockIdx.x;                 // n*WW + w
    const int    n    = nw >> 9;
    const int    w    = nw & 511;
    const int    cg   = blockIdx.y;
    const size_t base = (size_t)n * (HH * WW * CC) + (size_t)w * CC + (size_t)cg * CPB;

    if (threadIdx.x < CPB) {
        const float a = alpha[cg * CPB + threadIdx.x];
        sm[threadIdx.x] = 1.0f / (1.0f + expf(-a));   // sigmoid mix
    }

    // fp16 load from scratch: per h, 2 uint4 of 8 halves
    #pragma unroll
    for (int i = threadIdx.x; i < VECH; i += THREADS) {
        const int h = i >> 1;
        const int q = i & 1;
        uint4 v = *(const uint4*)(g_scratch + base + (size_t)h * (WW * CC) + q * 8);
        const __half2* hv = (const __half2*)&v;
        float* sp = s + h * CPB + q * 8;
        #pragma unroll
        for (int k = 0; k < 4; ++k) {
            float2 f = __half22float2(hv[k]);
            sp[2 * k]     = f.x;
            sp[2 * k + 1] = f.y;
        }
    }
    __syncthreads();

    iir_scan_tile(s, threadIdx.x);

    #pragma unroll
    for (int i = threadIdx.x; i < VEC; i += THREADS) {
        const int    h  = i >> 2;
        const int    c4 = i & 3;
        const size_t g  = base + (size_t)h * (WW * CC) + c4 * 4;
        const float4 xv = *(const float4*)(x + g);
        const float4 yv = s4[h * 4 + c4];
        const float4 mv = *(const float4*)(&sm[c4 * 4]);
        float4 o;
        o.x = fmaf(mv.x, yv.x - xv.x, xv.x);
        o.y = fmaf(mv.y, yv.y - xv.y, xv.y);
        o.z = fmaf(mv.z, yv.z - xv.z, xv.z);
        o.w = fmaf(mv.w, yv.w - xv.w, xv.w);
        *(float4*)(out + g) = o;
    }
}

extern "C" void kernel_launch(void* const* d_in, const int* in_sizes, int n_in,
                              void* d_out, int out_size) {
    const float* x     = (const float*)d_in[0];
    const float* alpha = (const float*)d_in[1];
    float*       out   = (float*)d_out;

    dim3 grid1(NN * HH, CC / CPB);
    pass1_kernel<<<grid1, THREADS, SMEM_BYTES>>>(x);

    dim3 grid2(NN * WW, CC / CPB);
    pass2_kernel<<<grid2, THREADS, SMEM_BYTES>>>(x, alpha, out);
}

// round 4
// speedup vs baseline: 1.6595x; 1.6595x over previous
#include <cuda_runtime.h>
#include <cuda_fp16.h>
#include <math.h>

// Problem dims (fixed by the dataset)
#define NN 4
#define HH 512
#define WW 512
#define CC 64

#define CPB     32                 // channels per block (128B fp32 per row-step)
#define THREADS 512
#define ROWLEN  512                // scan length (W in pass1, H in pass2)
#define NCHUNK  (THREADS / CPB)    // 16
#define CLEN    (ROWLEN / NCHUNK)  // 32
#define LWARM   16                 // warm-up: err ~ 0.5^17 ~ 8e-6 (under fp16 floor)
#define VEC     (ROWLEN * CPB / 4) // float4s per fp32 tile = 4096
#define VECH    (ROWLEN * CPB / 8) // uint4s (8 halves) per fp16 tile = 2048
#define SMEM_BYTES (ROWLEN * CPB * 4) // 65536

// Intermediate (W-filtered) image in fp16, same NHWC index space as x.
__device__ __half g_scratch[(size_t)NN * HH * WW * CC];

// Forward+backward first-order IIR (a=b=0.5) over a ROWLEN x CPB fp32 tile
// in shared memory, in place. Chunk-parallel with clamped warm-ups; boundary
// chunks are EXACT (carry = s[0] = x[0] forward; carry = s[L-1] = y_f[L-1]
// backward, matching the reference inits). Interior carries decay their
// initial guess over >= LWARM steps.
__device__ __forceinline__ void iir_scan_tile(float* s, int tid) {
    const int c     = tid & (CPB - 1);
    const int chunk = tid / CPB;          // 0..NCHUNK-1
    const int w0    = chunk * CLEN;
    const int w1    = w0 + CLEN;

    // ---- forward warm-up (read-only) ----
    int ws = w0 - LWARM; if (ws < 0) ws = 0;
    float carry = s[ws * CPB + c];
    for (int w = ws; w < w0; ++w)
        carry = fmaf(0.5f, carry, 0.5f * s[w * CPB + c]);
    __syncthreads();

    // ---- forward scan, in place (own chunk only) ----
    #pragma unroll
    for (int w = w0; w < w1; ++w) {
        carry = fmaf(0.5f, carry, 0.5f * s[w * CPB + c]);
        s[w * CPB + c] = carry;
    }
    __syncthreads();

    // ---- backward warm-up (read-only on finalized y_f) ----
    int we = w1 - 1 + LWARM; if (we > ROWLEN - 1) we = ROWLEN - 1;
    carry = s[we * CPB + c];
    for (int w = we - 1; w >= w1; --w)
        carry = fmaf(0.5f, carry, 0.5f * s[w * CPB + c]);
    __syncthreads();

    // ---- backward scan, in place (own chunk only) ----
    #pragma unroll
    for (int w = w1 - 1; w >= w0; --w) {
        carry = fmaf(0.5f, carry, 0.5f * s[w * CPB + c]);
        s[w * CPB + c] = carry;
    }
    __syncthreads();
}

// Pass 1: IIR along W for ONE batch image. One block per (row h, cgroup).
__global__ void __launch_bounds__(THREADS)
pass1_kernel(const float* __restrict__ x, int n) {
    extern __shared__ float s[];
    float4* s4 = reinterpret_cast<float4*>(s);

    const int    h    = blockIdx.x;
    const int    cg   = blockIdx.y;
    const size_t base = ((size_t)n * HH + h) * (WW * CC) + (size_t)cg * CPB;

    #pragma unroll
    for (int i = threadIdx.x; i < VEC; i += THREADS) {
        const int w  = i >> 3;                      // 8 float4 per w
        const int c4 = i & 7;
        s4[w * 8 + c4] = *(const float4*)(x + base + (size_t)w * CC + c4 * 4);
    }
    __syncthreads();

    iir_scan_tile(s, threadIdx.x);

    // fp16 store: per w, 32 ch = 64B = 4 uint4 (8 halves each)
    #pragma unroll
    for (int i = threadIdx.x; i < VECH; i += THREADS) {
        const int w = i >> 2;
        const int q = i & 3;
        const float* sp = s + w * CPB + q * 8;
        __half2 hv[4];
        #pragma unroll
        for (int k = 0; k < 4; ++k)
            hv[k] = __floats2half2_rn(sp[2 * k], sp[2 * k + 1]);
        *(uint4*)(g_scratch + base + (size_t)w * CC + q * 8) = *(uint4*)hv;
    }
}

// Pass 2: IIR along H for ONE batch image (fp16 scratch in, fp32 scan),
// then residual mix with x -> out.
__global__ void __launch_bounds__(THREADS)
pass2_kernel(const float* __restrict__ x,
             const float* __restrict__ alpha,
             float*       __restrict__ out, int n) {
    extern __shared__ float s[];
    float4* s4 = reinterpret_cast<float4*>(s);
    __shared__ __align__(16) float sm[CPB];

    const int    w    = blockIdx.x;
    const int    cg   = blockIdx.y;
    const size_t base = (size_t)n * (HH * WW * CC) + (size_t)w * CC + (size_t)cg * CPB;

    if (threadIdx.x < CPB) {
        const float a = alpha[cg * CPB + threadIdx.x];
        sm[threadIdx.x] = 1.0f / (1.0f + expf(-a));   // sigmoid mix
    }

    // fp16 load from scratch: per h, 4 uint4 of 8 halves (64B/row-step)
    #pragma unroll
    for (int i = threadIdx.x; i < VECH; i += THREADS) {
        const int h = i >> 2;
        const int q = i & 3;
        uint4 v = *(const uint4*)(g_scratch + base + (size_t)h * (WW * CC) + q * 8);
        const __half2* hv = (const __half2*)&v;
        float* sp = s + h * CPB + q * 8;
        #pragma unroll
        for (int k = 0; k < 4; ++k) {
            float2 f = __half22float2(hv[k]);
            sp[2 * k]     = f.x;
            sp[2 * k + 1] = f.y;
        }
    }
    __syncthreads();

    iir_scan_tile(s, threadIdx.x);

    #pragma unroll
    for (int i = threadIdx.x; i < VEC; i += THREADS) {
        const int    h  = i >> 3;
        const int    c4 = i & 7;
        const size_t g  = base + (size_t)h * (WW * CC) + c4 * 4;
        const float4 xv = *(const float4*)(x + g);
        const float4 yv = s4[h * 8 + c4];
        const float4 mv = *(const float4*)(&sm[c4 * 4]);
        float4 o;
        o.x = fmaf(mv.x, yv.x - xv.x, xv.x);
        o.y = fmaf(mv.y, yv.y - xv.y, xv.y);
        o.z = fmaf(mv.z, yv.z - xv.z, xv.z);
        o.w = fmaf(mv.w, yv.w - xv.w, xv.w);
        *(float4*)(out + g) = o;
    }
}

extern "C" void kernel_launch(void* const* d_in, const int* in_sizes, int n_in,
                              void* d_out, int out_size) {
    const float* x     = (const float*)d_in[0];
    const float* alpha = (const float*)d_in[1];
    float*       out   = (float*)d_out;

    // >48KB dynamic smem opt-in (idempotent, capture-safe).
    cudaFuncSetAttribute(pass1_kernel,
                         cudaFuncAttributeMaxDynamicSharedMemorySize, SMEM_BYTES);
    cudaFuncSetAttribute(pass2_kernel,
                         cudaFuncAttributeMaxDynamicSharedMemorySize, SMEM_BYTES);

    // Per-image pipelining: pass2(n) consumes pass1(n)'s fp16 scratch while
    // it (and much of x's slab) is still resident in the ~126MB L2.
    dim3 grid1(HH, CC / CPB);
    dim3 grid2(WW, CC / CPB);
    for (int n = 0; n < NN; ++n) {
        pass1_kernel<<<grid1, THREADS, SMEM_BYTES>>>(x, n);
        pass2_kernel<<<grid2, THREADS, SMEM_BYTES>>>(x, alpha, out, n);
    }
}

// round 5
// speedup vs baseline: 1.9320x; 1.1642x over previous
#include <cuda_runtime.h>
#include <cuda_fp16.h>
#include <math.h>

// Problem dims (fixed by the dataset)
#define NN 4
#define HH 512
#define WW 512
#define CC 64

#define CPB     32                 // channels per block (128B fp32 per row-step)
#define THREADS 512
#define ROWLEN  512                // scan length (W in pass1, H in pass2)
#define NCHUNK  (THREADS / CPB)    // 16
#define CLEN    (ROWLEN / NCHUNK)  // 32
#define LWARM   16                 // warm-up: err ~ 0.5^17 ~ 8e-6 (under fp16 floor)
#define VECH    (ROWLEN * CPB / 8) // uint4s (8 halves) per fp16 tile = 2048
#define VEC     (ROWLEN * CPB / 4) // float4-granule work items (epilogue) = 4096
#define SMEM_BYTES (ROWLEN * CPB * 2) // 32768 (fp16 tile -> 4 CTAs/SM)

// Intermediate (W-filtered) image in fp16, same NHWC index space as x.
__device__ __half g_scratch[(size_t)NN * HH * WW * CC];

// Forward+backward first-order IIR (a=b=0.5) over a ROWLEN x CPB tile held
// in fp16 shared memory, in place. The carry chain is fp32 in registers;
// only per-element storage rounds to fp16. Chunk-parallel with clamped
// warm-ups; boundary chunks are EXACT w.r.t. the reference inits
// (carry = s[0] = x[0] forward; carry = s[L-1] = y_f[L-1] backward).
__device__ __forceinline__ void iir_scan_tile_h(__half* s, int tid) {
    const int c     = tid & (CPB - 1);
    const int chunk = tid / CPB;          // 0..NCHUNK-1
    const int w0    = chunk * CLEN;
    const int w1    = w0 + CLEN;

    // ---- forward warm-up (read-only) ----
    int ws = w0 - LWARM; if (ws < 0) ws = 0;
    float carry = __half2float(s[ws * CPB + c]);
    for (int w = ws; w < w0; ++w)
        carry = fmaf(0.5f, carry, 0.5f * __half2float(s[w * CPB + c]));
    __syncthreads();

    // ---- forward scan, in place (own chunk only) ----
    #pragma unroll
    for (int w = w0; w < w1; ++w) {
        carry = fmaf(0.5f, carry, 0.5f * __half2float(s[w * CPB + c]));
        s[w * CPB + c] = __float2half_rn(carry);
    }
    __syncthreads();

    // ---- backward warm-up (read-only on finalized y_f) ----
    int we = w1 - 1 + LWARM; if (we > ROWLEN - 1) we = ROWLEN - 1;
    carry = __half2float(s[we * CPB + c]);
    for (int w = we - 1; w >= w1; --w)
        carry = fmaf(0.5f, carry, 0.5f * __half2float(s[w * CPB + c]));
    __syncthreads();

    // ---- backward scan, in place (own chunk only) ----
    #pragma unroll
    for (int w = w1 - 1; w >= w0; --w) {
        carry = fmaf(0.5f, carry, 0.5f * __half2float(s[w * CPB + c]));
        s[w * CPB + c] = __float2half_rn(carry);
    }
    __syncthreads();
}

// Pass 1: IIR along W. One block per (n*H row, channel-group of 32).
// Reads x (fp32) -> fp16 tile -> scan -> fp16 scratch (raw copy).
__global__ void __launch_bounds__(THREADS, 4)
pass1_kernel(const float* __restrict__ x) {
    extern __shared__ __half s16[];
    uint4* s4 = reinterpret_cast<uint4*>(s16);

    const int    nh   = blockIdx.x;                 // n*HH + h
    const int    cg   = blockIdx.y;                 // channel group
    const size_t base = (size_t)nh * (WW * CC) + (size_t)cg * CPB;

    // Load + fp32->fp16 convert: thread handles 8 channels (two float4).
    #pragma unroll
    for (int i = threadIdx.x; i < VECH; i += THREADS) {
        const int w = i >> 2;
        const int q = i & 3;
        const float4 a = *(const float4*)(x + base + (size_t)w * CC + q * 8);
        const float4 b = *(const float4*)(x + base + (size_t)w * CC + q * 8 + 4);
        __half2 hv[4];
        hv[0] = __floats2half2_rn(a.x, a.y);
        hv[1] = __floats2half2_rn(a.z, a.w);
        hv[2] = __floats2half2_rn(b.x, b.y);
        hv[3] = __floats2half2_rn(b.z, b.w);
        s4[w * 4 + q] = *(uint4*)hv;
    }
    __syncthreads();

    iir_scan_tile_h(s16, threadIdx.x);

    // Raw fp16 copy smem -> scratch: per w, 32 ch = 64B = 4 uint4.
    #pragma unroll
    for (int i = threadIdx.x; i < VECH; i += THREADS) {
        const int w = i >> 2;
        const int q = i & 3;
        *(uint4*)(g_scratch + base + (size_t)w * CC + q * 8) = s4[w * 4 + q];
    }
}

// Pass 2: IIR along H on the scratch (raw fp16 copy in), residual mix -> out.
__global__ void __launch_bounds__(THREADS, 4)
pass2_kernel(const float* __restrict__ x,
             const float* __restrict__ alpha,
             float*       __restrict__ out) {
    extern __shared__ __half s16[];
    uint4* s4 = reinterpret_cast<uint4*>(s16);
    __shared__ __align__(16) float sm[CPB];

    const int    nw   = blockIdx.x;                 // n*WW + w
    const int    n    = nw >> 9;
    const int    w    = nw & 511;
    const int    cg   = blockIdx.y;
    const size_t base = (size_t)n * (HH * WW * CC) + (size_t)w * CC + (size_t)cg * CPB;

    if (threadIdx.x < CPB) {
        const float a = alpha[cg * CPB + threadIdx.x];
        sm[threadIdx.x] = 1.0f / (1.0f + expf(-a));   // sigmoid mix
    }

    // Raw fp16 copy scratch -> smem: per h, 4 uint4 (64B row-step).
    #pragma unroll
    for (int i = threadIdx.x; i < VECH; i += THREADS) {
        const int h = i >> 2;
        const int q = i & 3;
        s4[h * 4 + q] = *(const uint4*)(g_scratch + base + (size_t)h * (WW * CC) + q * 8);
    }
    __syncthreads();

    iir_scan_tile_h(s16, threadIdx.x);

    // Epilogue: y (fp16 smem) + x (fp32 gmem) -> out (fp32).
    #pragma unroll
    for (int i = threadIdx.x; i < VEC; i += THREADS) {
        const int    h  = i >> 3;
        const int    c4 = i & 7;
        const size_t g  = base + (size_t)h * (WW * CC) + c4 * 4;
        const float4 xv = *(const float4*)(x + g);
        const __half2* hp = (const __half2*)(s16 + h * CPB + c4 * 4);
        const float2 y0 = __half22float2(hp[0]);
        const float2 y1 = __half22float2(hp[1]);
        const float4 mv = *(const float4*)(&sm[c4 * 4]);
        float4 o;
        o.x = fmaf(mv.x, y0.x - xv.x, xv.x);
        o.y = fmaf(mv.y, y0.y - xv.y, xv.y);
        o.z = fmaf(mv.z, y1.x - xv.z, xv.z);
        o.w = fmaf(mv.w, y1.y - xv.w, xv.w);
        *(float4*)(out + g) = o;
    }
}

extern "C" void kernel_launch(void* const* d_in, const int* in_sizes, int n_in,
                              void* d_out, int out_size) {
    const float* x     = (const float*)d_in[0];
    const float* alpha = (const float*)d_in[1];
    float*       out   = (float*)d_out;

    dim3 grid1(NN * HH, CC / CPB);
    pass1_kernel<<<grid1, THREADS, SMEM_BYTES>>>(x);

    dim3 grid2(NN * WW, CC / CPB);
    pass2_kernel<<<grid2, THREADS, SMEM_BYTES>>>(x, alpha, out);
}